// round 3
// baseline (speedup 1.0000x reference)
#include <cuda_runtime.h>
#include <cuda_fp16.h>

// ---------------------------------------------------------------------------
// UnfoldindAndAttention: 8 rounds of normalized graph propagation over
// N=50000 nodes, D=64 features, E=1.6M edges, attention reweighting after
// round 4. Pull-based CSR (grouped by dst): no float atomics, L2-resident.
// R3: fp16 gather operand for BOTH aggregation and attention (128B/edge),
// precomputed 0.5*rx*X term, streaming load hints, 8-way unroll.
// ---------------------------------------------------------------------------

#define NMAX 50048
#define EMAX 1600000
#define DV   16          // 64 floats = 16 float4 (or 16 uint2 fp16) per node row

static __device__ int    g_cnt[NMAX];
static __device__ int    g_cursor[NMAX];
static __device__ int    g_rowptr[NMAX + 1];
static __device__ int    g_bsum[256];
static __device__ int    g_boff[256];
static __device__ int    g_col[EMAX];          // src index per CSR slot
static __device__ float  g_w[EMAX];            // attention weight per CSR slot
static __device__ float  g_rs[NMAX];           // (deg+1)^-0.5
static __device__ float4 g_Y[NMAX * DV];       // current Y (fp32)
static __device__ float4 g_Xr[NMAX * DV];      // 0.5 * rx * X (fp32)
static __device__ uint2  g_YsA[NMAX * DV];     // rs*Y in fp16 ping
static __device__ uint2  g_YsB[NMAX * DV];     // pong
static __device__ uint2  g_Yh[NMAX * DV];      // fp16 copy of Y after step 3

// -------------------------------------------------------------- setup kernels

__global__ void k_zero(int N) {
    int i = blockIdx.x * 256 + threadIdx.x;
    if (i < N) { g_cnt[i] = 0; g_cursor[i] = 0; }
}

__global__ void k_count(const int* __restrict__ dst, int E) {
    int e = blockIdx.x * 256 + threadIdx.x;
    if (e < E) atomicAdd(&g_cnt[dst[e]], 1);
}

// Exclusive block scan (blockDim = 1024). mode 0: cnt -> rowptr (+bsum),
// mode 1: bsum -> boff.
__global__ void k_scan(int mode, int n) {
    const int* in = mode ? g_bsum : g_cnt;
    int* out      = mode ? g_boff : g_rowptr;
    __shared__ int ws[32];
    int g    = blockIdx.x * 1024 + threadIdx.x;
    int lane = threadIdx.x & 31;
    int wid  = threadIdx.x >> 5;
    int v = (g < n) ? in[g] : 0;
    int x = v;
#pragma unroll
    for (int o = 1; o < 32; o <<= 1) {
        int y = __shfl_up_sync(0xFFFFFFFFu, x, o);
        if (lane >= o) x += y;
    }
    if (lane == 31) ws[wid] = x;
    __syncthreads();
    if (wid == 0) {
        int s = ws[lane];
#pragma unroll
        for (int o = 1; o < 32; o <<= 1) {
            int y = __shfl_up_sync(0xFFFFFFFFu, s, o);
            if (lane >= o) s += y;
        }
        ws[lane] = s;
    }
    __syncthreads();
    int boff = wid ? ws[wid - 1] : 0;
    if (g < n) out[g] = boff + x - v;          // exclusive
    if (mode == 0 && threadIdx.x == 0) g_bsum[blockIdx.x] = ws[31];
}

__global__ void k_addoff(int n, int E) {
    int g = blockIdx.x * 1024 + threadIdx.x;
    if (g < n) g_rowptr[g] += g_boff[blockIdx.x];
    if (blockIdx.x == 0 && threadIdx.x == 0) g_rowptr[n] = E;
}

__global__ void k_scatter(const int* __restrict__ src, const int* __restrict__ dst, int E) {
    int e = blockIdx.x * 256 + threadIdx.x;
    if (e < E) {
        int v   = dst[e];
        int off = atomicAdd(&g_cursor[v], 1);
        g_col[g_rowptr[v] + off] = src[e];
    }
}

static __device__ __forceinline__ uint2 pack4(float a, float b, float c, float d) {
    half2 h0 = __floats2half2_rn(a, b);
    half2 h1 = __floats2half2_rn(c, d);
    uint2 r;
    r.x = *(unsigned int*)&h0;
    r.y = *(unsigned int*)&h1;
    return r;
}

// Y0 = X; rs/Xr from integer in-degree; YsA = fp16(rs * X)
__global__ void k_init(const float4* __restrict__ X4, int N) {
    int t = blockIdx.x * 256 + threadIdx.x;
    if (t >= N * DV) return;
    int v = t >> 4;
    float deg = (float)g_cnt[v];
    float rs  = 1.0f / sqrtf(deg + 1.0f);
    float hrx = 0.5f / (deg + 1.0f);
    if ((t & 15) == 0) g_rs[v] = rs;
    float4 x = X4[t];
    g_Y[t]   = x;
    g_Xr[t]  = make_float4(x.x * hrx, x.y * hrx, x.z * hrx, x.w * hrx);
    g_YsA[t] = pack4(x.x * rs, x.y * rs, x.z * rs, x.w * rs);
}

// -------------------------------------------------------------- propagation

static __device__ __forceinline__ void acc4(float& ax, float& ay, float& az, float& aw,
                                            float w, uint2 q) {
    float2 f0 = __half22float2(*(half2*)&q.x);
    float2 f1 = __half22float2(*(half2*)&q.y);
    ax = fmaf(w, f0.x, ax);
    ay = fmaf(w, f0.y, ay);
    az = fmaf(w, f1.x, az);
    aw = fmaf(w, f1.y, aw);
}

// One propagation step, fused: pull-aggregate + epilogue + next-step operand.
// Half-warp (16 lanes, 4 features each) per node.
template<bool HAS_W, bool WRITE_YS, bool WRITE_YH, bool TO_OUT>
__global__ void __launch_bounds__(256)
k_agg(float4* __restrict__ outp, int par, int N) {
    int t = blockIdx.x * 256 + threadIdx.x;
    int v = t >> 4;
    if (v >= N) return;
    int l = t & 15;
    const uint2* __restrict__ Yin = par ? g_YsB : g_YsA;
    uint2* Yso                    = par ? g_YsA : g_YsB;

    int s  = g_rowptr[v];
    int se = g_rowptr[v + 1];
    float ax = 0.f, ay = 0.f, az = 0.f, aw = 0.f;

    for (; s + 8 <= se; s += 8) {
#pragma unroll
        for (int u = 0; u < 8; u += 4) {
            int c0 = g_col[s + u], c1 = g_col[s + u + 1];
            int c2 = g_col[s + u + 2], c3 = g_col[s + u + 3];
            float w0 = 1.f, w1 = 1.f, w2 = 1.f, w3 = 1.f;
            if (HAS_W) {
                w0 = g_w[s + u];     w1 = g_w[s + u + 1];
                w2 = g_w[s + u + 2]; w3 = g_w[s + u + 3];
            }
            uint2 q0 = __ldcs(&Yin[c0 * DV + l]);
            uint2 q1 = __ldcs(&Yin[c1 * DV + l]);
            uint2 q2 = __ldcs(&Yin[c2 * DV + l]);
            uint2 q3 = __ldcs(&Yin[c3 * DV + l]);
            acc4(ax, ay, az, aw, w0, q0);
            acc4(ax, ay, az, aw, w1, q1);
            acc4(ax, ay, az, aw, w2, q2);
            acc4(ax, ay, az, aw, w3, q3);
        }
    }
    for (; s < se; ++s) {
        int c    = g_col[s];
        float wv = HAS_W ? g_w[s] : 1.f;
        acc4(ax, ay, az, aw, wv, __ldcs(&Yin[c * DV + l]));
    }

    float rs  = g_rs[v];
    float hrs = 0.5f * rs;
    float4 y  = g_Y[t];
    float4 hx = g_Xr[t];
    float4 yn;
    yn.x = 0.5f * y.x + hrs * ax + hx.x;
    yn.y = 0.5f * y.y + hrs * ay + hx.y;
    yn.z = 0.5f * y.z + hrs * az + hx.z;
    yn.w = 0.5f * y.w + hrs * aw + hx.w;

    if (TO_OUT) outp[t] = yn; else g_Y[t] = yn;
    if (WRITE_YS) Yso[t] = pack4(yn.x * rs, yn.y * rs, yn.z * rs, yn.w * rs);
    if (WRITE_YH) g_Yh[t] = pack4(yn.x, yn.y, yn.z, yn.w);
}

// -------------------------------------------------------------- attention

// Per node: Zv from fp32 Y (own row), neighbors gathered from fp16 Yh.
// 16-lane shfl reduction of |dZ|^2; lane 0 computes w and weighted degree.
// Fused rescale: new rs, new Xr = 0.5*rx*X, and YsA = rs_new * Y.
__global__ void __launch_bounds__(256)
k_attn(const float4* __restrict__ X4, const float4* __restrict__ etas4, int N) {
    int t = blockIdx.x * 256 + threadIdx.x;
    int v = t >> 4;
    if (v >= N) return;
    int l = t & 15;
    unsigned mask = 0xFFFFu << (threadIdx.x & 16);

    float4 et = etas4[l];
    float4 yv = g_Y[t];
    float4 zv = make_float4(yv.x * et.x, yv.y * et.y, yv.z * et.z, yv.w * et.w);

    float degw = 0.f;
    int se = g_rowptr[v + 1];
    for (int s = g_rowptr[v]; s < se; ++s) {
        int c    = g_col[s];
        uint2 q  = __ldcs(&g_Yh[c * DV + l]);
        float2 f0 = __half22float2(*(half2*)&q.x);
        float2 f1 = __half22float2(*(half2*)&q.y);
        float dx = zv.x - f0.x * et.x;
        float dy = zv.y - f0.y * et.y;
        float dz = zv.z - f1.x * et.z;
        float dw = zv.w - f1.y * et.w;
        float p = dx * dx + dy * dy + dz * dz + dw * dw;
        p += __shfl_xor_sync(mask, p, 8);
        p += __shfl_xor_sync(mask, p, 4);
        p += __shfl_xor_sync(mask, p, 2);
        p += __shfl_xor_sync(mask, p, 1);
        if (l == 0) {
            float wv = (p > 2.0f) ? 0.2f : 0.5f / sqrtf(p + 1e-7f);
            g_w[s] = wv;
            degw  += wv;
        }
    }
    // fused rescale: broadcast degw from lane 0 of each 16-lane group
    float deg = __shfl_sync(0xFFFFFFFFu, degw, 0, 16);
    float rs  = 1.0f / sqrtf(deg + 1.0f);
    float hrx = 0.5f / (deg + 1.0f);
    if (l == 0) g_rs[v] = rs;
    float4 x = X4[t];
    g_Xr[t]  = make_float4(x.x * hrx, x.y * hrx, x.z * hrx, x.w * hrx);
    g_YsA[t] = pack4(yv.x * rs, yv.y * rs, yv.z * rs, yv.w * rs);
}

// -------------------------------------------------------------- launcher

extern "C" void kernel_launch(void* const* d_in, const int* in_sizes, int n_in,
                              void* d_out, int out_size) {
    const float4* X4    = (const float4*)d_in[0];
    const float4* etas4 = (const float4*)d_in[1];
    const int*    src   = (const int*)d_in[2];
    const int*    dst   = (const int*)d_in[3];
    float4*       out4  = (float4*)d_out;

    int N = in_sizes[0] / 64;
    int E = in_sizes[2];

    int bN  = (N + 255) / 256;
    int bE  = (E + 255) / 256;
    int NB  = (N + 1023) / 1024;
    int bT  = (N * DV + 255) / 256;

    // ---- CSR build ----
    k_zero<<<bN, 256>>>(N);
    k_count<<<bE, 256>>>(dst, E);
    k_scan<<<NB, 1024>>>(0, N);
    k_scan<<<1, 1024>>>(1, NB);
    k_addoff<<<NB, 1024>>>(N, E);
    k_scatter<<<bE, 256>>>(src, dst, E);
    k_init<<<bT, 256>>>(X4, N);

    // ---- steps 0..3: w == 1 (step 3 writes fp16 Y copy for attention) ----
    k_agg<false, true,  false, false><<<bT, 256>>>(out4, 0, N);
    k_agg<false, true,  false, false><<<bT, 256>>>(out4, 1, N);
    k_agg<false, true,  false, false><<<bT, 256>>>(out4, 0, N);
    k_agg<false, false, true,  false><<<bT, 256>>>(out4, 1, N);

    // ---- attention after round 4 (rescale + Xr + YsA fused) ----
    k_attn<<<bT, 256>>>(X4, etas4, N);

    // ---- steps 4..7: attention weights ----
    k_agg<true, true,  false, false><<<bT, 256>>>(out4, 0, N);
    k_agg<true, true,  false, false><<<bT, 256>>>(out4, 1, N);
    k_agg<true, true,  false, false><<<bT, 256>>>(out4, 0, N);
    k_agg<true, false, false, true ><<<bT, 256>>>(out4, 1, N);
}

// round 5
// speedup vs baseline: 1.0071x; 1.0071x over previous
#include <cuda_runtime.h>
#include <cuda_fp16.h>

// ---------------------------------------------------------------------------
// UnfoldindAndAttention: 8 rounds of normalized graph propagation over
// N=50000 nodes, D=64 features, E=1.6M edges, attention reweighting after
// round 4. Pull-based CSR (grouped by dst): no float atomics, L2-resident.
// R4 (resubmit; prior run hit an infra failure): like R3 (fp16 gathers for
// agg+attention, precomputed 0.5*rx*X) but with read-only cached gathers
// (__ldg) -- mean in-degree 32 means every operand row has ~32x temporal
// reuse; L1 must stay in play.
// ---------------------------------------------------------------------------

#define NMAX 50048
#define EMAX 1600000
#define DV   16          // 64 floats = 16 float4 (or 16 uint2 fp16) per node row

static __device__ int    g_cnt[NMAX];
static __device__ int    g_cursor[NMAX];
static __device__ int    g_rowptr[NMAX + 1];
static __device__ int    g_bsum[256];
static __device__ int    g_boff[256];
static __device__ int    g_col[EMAX];          // src index per CSR slot
static __device__ float  g_w[EMAX];            // attention weight per CSR slot
static __device__ float  g_rs[NMAX];           // (deg+1)^-0.5
static __device__ float4 g_Y[NMAX * DV];       // current Y (fp32)
static __device__ float4 g_Xr[NMAX * DV];      // 0.5 * rx * X (fp32)
static __device__ uint2  g_YsA[NMAX * DV];     // rs*Y in fp16 ping
static __device__ uint2  g_YsB[NMAX * DV];     // pong
static __device__ uint2  g_Yh[NMAX * DV];      // fp16 copy of Y after step 3

// -------------------------------------------------------------- setup kernels

__global__ void k_zero(int N) {
    int i = blockIdx.x * 256 + threadIdx.x;
    if (i < N) { g_cnt[i] = 0; g_cursor[i] = 0; }
}

__global__ void k_count(const int* __restrict__ dst, int E) {
    int e = blockIdx.x * 256 + threadIdx.x;
    if (e < E) atomicAdd(&g_cnt[dst[e]], 1);
}

// Exclusive block scan (blockDim = 1024). mode 0: cnt -> rowptr (+bsum),
// mode 1: bsum -> boff.
__global__ void k_scan(int mode, int n) {
    const int* in = mode ? g_bsum : g_cnt;
    int* out      = mode ? g_boff : g_rowptr;
    __shared__ int ws[32];
    int g    = blockIdx.x * 1024 + threadIdx.x;
    int lane = threadIdx.x & 31;
    int wid  = threadIdx.x >> 5;
    int v = (g < n) ? in[g] : 0;
    int x = v;
#pragma unroll
    for (int o = 1; o < 32; o <<= 1) {
        int y = __shfl_up_sync(0xFFFFFFFFu, x, o);
        if (lane >= o) x += y;
    }
    if (lane == 31) ws[wid] = x;
    __syncthreads();
    if (wid == 0) {
        int s = ws[lane];
#pragma unroll
        for (int o = 1; o < 32; o <<= 1) {
            int y = __shfl_up_sync(0xFFFFFFFFu, s, o);
            if (lane >= o) s += y;
        }
        ws[lane] = s;
    }
    __syncthreads();
    int boff = wid ? ws[wid - 1] : 0;
    if (g < n) out[g] = boff + x - v;          // exclusive
    if (mode == 0 && threadIdx.x == 0) g_bsum[blockIdx.x] = ws[31];
}

__global__ void k_addoff(int n, int E) {
    int g = blockIdx.x * 1024 + threadIdx.x;
    if (g < n) g_rowptr[g] += g_boff[blockIdx.x];
    if (blockIdx.x == 0 && threadIdx.x == 0) g_rowptr[n] = E;
}

__global__ void k_scatter(const int* __restrict__ src, const int* __restrict__ dst, int E) {
    int e = blockIdx.x * 256 + threadIdx.x;
    if (e < E) {
        int v   = dst[e];
        int off = atomicAdd(&g_cursor[v], 1);
        g_col[g_rowptr[v] + off] = src[e];
    }
}

static __device__ __forceinline__ uint2 pack4(float a, float b, float c, float d) {
    half2 h0 = __floats2half2_rn(a, b);
    half2 h1 = __floats2half2_rn(c, d);
    uint2 r;
    r.x = *(unsigned int*)&h0;
    r.y = *(unsigned int*)&h1;
    return r;
}

// Y0 = X; rs/Xr from integer in-degree; YsA = fp16(rs * X)
__global__ void k_init(const float4* __restrict__ X4, int N) {
    int t = blockIdx.x * 256 + threadIdx.x;
    if (t >= N * DV) return;
    int v = t >> 4;
    float deg = (float)g_cnt[v];
    float rs  = 1.0f / sqrtf(deg + 1.0f);
    float hrx = 0.5f / (deg + 1.0f);
    if ((t & 15) == 0) g_rs[v] = rs;
    float4 x = X4[t];
    g_Y[t]   = x;
    g_Xr[t]  = make_float4(x.x * hrx, x.y * hrx, x.z * hrx, x.w * hrx);
    g_YsA[t] = pack4(x.x * rs, x.y * rs, x.z * rs, x.w * rs);
}

// -------------------------------------------------------------- propagation

static __device__ __forceinline__ void acc4(float& ax, float& ay, float& az, float& aw,
                                            float w, uint2 q) {
    float2 f0 = __half22float2(*(half2*)&q.x);
    float2 f1 = __half22float2(*(half2*)&q.y);
    ax = fmaf(w, f0.x, ax);
    ay = fmaf(w, f0.y, ay);
    az = fmaf(w, f1.x, az);
    aw = fmaf(w, f1.y, aw);
}

// One propagation step, fused: pull-aggregate + epilogue + next-step operand.
// Half-warp (16 lanes, 4 features each) per node.
template<bool HAS_W, bool WRITE_YS, bool WRITE_YH, bool TO_OUT>
__global__ void __launch_bounds__(256)
k_agg(float4* __restrict__ outp, int par, int N) {
    int t = blockIdx.x * 256 + threadIdx.x;
    int v = t >> 4;
    if (v >= N) return;
    int l = t & 15;
    const uint2* __restrict__ Yin = par ? g_YsB : g_YsA;
    uint2* Yso                    = par ? g_YsA : g_YsB;

    int s  = g_rowptr[v];
    int se = g_rowptr[v + 1];
    float ax = 0.f, ay = 0.f, az = 0.f, aw = 0.f;

    for (; s + 8 <= se; s += 8) {
#pragma unroll
        for (int u = 0; u < 8; u += 4) {
            int c0 = __ldg(&g_col[s + u]),     c1 = __ldg(&g_col[s + u + 1]);
            int c2 = __ldg(&g_col[s + u + 2]), c3 = __ldg(&g_col[s + u + 3]);
            float w0 = 1.f, w1 = 1.f, w2 = 1.f, w3 = 1.f;
            if (HAS_W) {
                w0 = __ldg(&g_w[s + u]);     w1 = __ldg(&g_w[s + u + 1]);
                w2 = __ldg(&g_w[s + u + 2]); w3 = __ldg(&g_w[s + u + 3]);
            }
            uint2 q0 = __ldg(&Yin[c0 * DV + l]);
            uint2 q1 = __ldg(&Yin[c1 * DV + l]);
            uint2 q2 = __ldg(&Yin[c2 * DV + l]);
            uint2 q3 = __ldg(&Yin[c3 * DV + l]);
            acc4(ax, ay, az, aw, w0, q0);
            acc4(ax, ay, az, aw, w1, q1);
            acc4(ax, ay, az, aw, w2, q2);
            acc4(ax, ay, az, aw, w3, q3);
        }
    }
    for (; s < se; ++s) {
        int c    = __ldg(&g_col[s]);
        float wv = HAS_W ? __ldg(&g_w[s]) : 1.f;
        acc4(ax, ay, az, aw, wv, __ldg(&Yin[c * DV + l]));
    }

    float rs  = g_rs[v];
    float hrs = 0.5f * rs;
    float4 y  = g_Y[t];
    float4 hx = g_Xr[t];
    float4 yn;
    yn.x = 0.5f * y.x + hrs * ax + hx.x;
    yn.y = 0.5f * y.y + hrs * ay + hx.y;
    yn.z = 0.5f * y.z + hrs * az + hx.z;
    yn.w = 0.5f * y.w + hrs * aw + hx.w;

    if (TO_OUT) outp[t] = yn; else g_Y[t] = yn;
    if (WRITE_YS) Yso[t] = pack4(yn.x * rs, yn.y * rs, yn.z * rs, yn.w * rs);
    if (WRITE_YH) g_Yh[t] = pack4(yn.x, yn.y, yn.z, yn.w);
}

// -------------------------------------------------------------- attention

// Per node: Zv from fp32 Y (own row), neighbors gathered from fp16 Yh.
// 16-lane shfl reduction of |dZ|^2; lane 0 computes w and weighted degree.
// Fused rescale: new rs, new Xr = 0.5*rx*X, and YsA = rs_new * Y.
__global__ void __launch_bounds__(256)
k_attn(const float4* __restrict__ X4, const float4* __restrict__ etas4, int N) {
    int t = blockIdx.x * 256 + threadIdx.x;
    int v = t >> 4;
    if (v >= N) return;
    int l = t & 15;
    unsigned mask = 0xFFFFu << (threadIdx.x & 16);

    float4 et = etas4[l];
    float4 yv = g_Y[t];
    float4 zv = make_float4(yv.x * et.x, yv.y * et.y, yv.z * et.z, yv.w * et.w);

    float degw = 0.f;
    int se = g_rowptr[v + 1];
    for (int s = g_rowptr[v]; s < se; ++s) {
        int c    = __ldg(&g_col[s]);
        uint2 q  = __ldg(&g_Yh[c * DV + l]);
        float2 f0 = __half22float2(*(half2*)&q.x);
        float2 f1 = __half22float2(*(half2*)&q.y);
        float dx = zv.x - f0.x * et.x;
        float dy = zv.y - f0.y * et.y;
        float dz = zv.z - f1.x * et.z;
        float dw = zv.w - f1.y * et.w;
        float p = dx * dx + dy * dy + dz * dz + dw * dw;
        p += __shfl_xor_sync(mask, p, 8);
        p += __shfl_xor_sync(mask, p, 4);
        p += __shfl_xor_sync(mask, p, 2);
        p += __shfl_xor_sync(mask, p, 1);
        if (l == 0) {
            float wv = (p > 2.0f) ? 0.2f : 0.5f / sqrtf(p + 1e-7f);
            g_w[s] = wv;
            degw  += wv;
        }
    }
    // fused rescale: broadcast degw from lane 0 of each 16-lane group
    float deg = __shfl_sync(0xFFFFFFFFu, degw, 0, 16);
    float rs  = 1.0f / sqrtf(deg + 1.0f);
    float hrx = 0.5f / (deg + 1.0f);
    if (l == 0) g_rs[v] = rs;
    float4 x = X4[t];
    g_Xr[t]  = make_float4(x.x * hrx, x.y * hrx, x.z * hrx, x.w * hrx);
    g_YsA[t] = pack4(yv.x * rs, yv.y * rs, yv.z * rs, yv.w * rs);
}

// -------------------------------------------------------------- launcher

extern "C" void kernel_launch(void* const* d_in, const int* in_sizes, int n_in,
                              void* d_out, int out_size) {
    const float4* X4    = (const float4*)d_in[0];
    const float4* etas4 = (const float4*)d_in[1];
    const int*    src   = (const int*)d_in[2];
    const int*    dst   = (const int*)d_in[3];
    float4*       out4  = (float4*)d_out;

    int N = in_sizes[0] / 64;
    int E = in_sizes[2];

    int bN  = (N + 255) / 256;
    int bE  = (E + 255) / 256;
    int NB  = (N + 1023) / 1024;
    int bT  = (N * DV + 255) / 256;

    // ---- CSR build ----
    k_zero<<<bN, 256>>>(N);
    k_count<<<bE, 256>>>(dst, E);
    k_scan<<<NB, 1024>>>(0, N);
    k_scan<<<1, 1024>>>(1, NB);
    k_addoff<<<NB, 1024>>>(N, E);
    k_scatter<<<bE, 256>>>(src, dst, E);
    k_init<<<bT, 256>>>(X4, N);

    // ---- steps 0..3: w == 1 (step 3 writes fp16 Y copy for attention) ----
    k_agg<false, true,  false, false><<<bT, 256>>>(out4, 0, N);
    k_agg<false, true,  false, false><<<bT, 256>>>(out4, 1, N);
    k_agg<false, true,  false, false><<<bT, 256>>>(out4, 0, N);
    k_agg<false, false, true,  false><<<bT, 256>>>(out4, 1, N);

    // ---- attention after round 4 (rescale + Xr + YsA fused) ----
    k_attn<<<bT, 256>>>(X4, etas4, N);

    // ---- steps 4..7: attention weights ----
    k_agg<true, true,  false, false><<<bT, 256>>>(out4, 0, N);
    k_agg<true, true,  false, false><<<bT, 256>>>(out4, 1, N);
    k_agg<true, true,  false, false><<<bT, 256>>>(out4, 0, N);
    k_agg<true, false, false, true ><<<bT, 256>>>(out4, 1, N);
}